// round 6
// baseline (speedup 1.0000x reference)
#include <cuda_runtime.h>

// QuanvLayer closed form:
//   z_i = cos(w_i) * cos(x_i)   (patch elements p00,p01,p10,p11)
//   out[q=0] = z1*z2*z3 ; out[q=1] = z0*z1 ; out[q=2] = z0*z1*z2 ; out[q=3] = z0*z1*z2*z3
//
// x: (128, 3, 128, 128) f32 ; weights: (1,4) f32 ; out: (128, 12, 64, 64) f32
//
// R5 (rerun after container failure): persistent grid + BALANCED warp-level
// partition. 12288 warp-chunks over 9472 warps: warp wg handles
// [wg*12288/9472, (wg+1)*12288/9472), so the 1-vs-2-chunk split is spread
// evenly over all blocks/SMs (R4 concentrated all second-round work in
// blocks 0..351 -> 25% tail, occ 73.6%).

#define B_ 128
#define C_ 3
#define H_ 128
#define W_ 128
#define HH 64
#define WH 64

#define NBLOCKS 1184
#define NTHREADS 256
#define NWARPS_BLK (NTHREADS / 32)                    // 8
#define WARPS_TOTAL (NBLOCKS * NWARPS_BLK)            // 9472
#define TOTAL_CHUNKS (B_ * C_ * HH * (WH / 4))        // 393216
#define WCHUNKS (TOTAL_CHUNKS / 32)                   // 12288

__global__ void __launch_bounds__(NTHREADS, 8)
quanv_kernel(const float* __restrict__ x,
             const float* __restrict__ w,
             float* __restrict__ out)
{
    const float cw0 = __cosf(__ldg(w + 0));
    const float cw1 = __cosf(__ldg(w + 1));
    const float cw2 = __cosf(__ldg(w + 2));
    const float cw3 = __cosf(__ldg(w + 3));

    const unsigned wg   = blockIdx.x * NWARPS_BLK + (threadIdx.x >> 5);
    const unsigned lane = threadIdx.x & 31;

    // balanced contiguous range of warp-chunks for this warp (1 or 2 chunks)
    const unsigned start = (unsigned)(((unsigned long long)wg * WCHUNKS) / WARPS_TOTAL);
    const unsigned end   = (unsigned)(((unsigned long long)(wg + 1) * WCHUNKS) / WARPS_TOTAL);

    for (unsigned wc = start; wc < end; wc++) {
        unsigned tid = wc * 32 + lane;               // chunk id in [0, 393216)

        // tid = (bc*HH + h2)*16 + w8 ; w8 covers 4 patches (8 input cols)
        int w8 = tid & 15;
        int h2 = (tid >> 4) & (HH - 1);
        int bc = tid >> 10;                          // b*C + c in [0, 384)

        const float* row = x + ((size_t)bc * H_ + 2 * h2) * W_ + 8 * w8;
        const float4 t0 = *reinterpret_cast<const float4*>(row);
        const float4 t1 = *reinterpret_cast<const float4*>(row + 4);
        const float4 b0 = *reinterpret_cast<const float4*>(row + W_);
        const float4 b1 = *reinterpret_cast<const float4*>(row + W_ + 4);

        float top[8] = {t0.x, t0.y, t0.z, t0.w, t1.x, t1.y, t1.z, t1.w};
        float bot[8] = {b0.x, b0.y, b0.z, b0.w, b1.x, b1.y, b1.z, b1.w};

        float o0[4], o1[4], o2[4], o3[4];
        #pragma unroll
        for (int p = 0; p < 4; p++) {
            float z0 = cw0 * __cosf(top[2*p]);
            float z1 = cw1 * __cosf(top[2*p + 1]);
            float z2 = cw2 * __cosf(bot[2*p]);
            float z3 = cw3 * __cosf(bot[2*p + 1]);
            float q1 = z0 * z1;
            float q2 = q1 * z2;
            float q3 = q2 * z3;
            float q0 = z1 * z2 * z3;
            o0[p] = q0; o1[p] = q1; o2[p] = q2; o3[p] = q3;
        }

        // out[((4*bc + q)*HH + h2)*WH + 4*w8], plane stride HH*WH = 4096
        float* o = out + (((size_t)4 * bc) * HH + h2) * WH + 4 * w8;
        *reinterpret_cast<float4*>(o)           = make_float4(o0[0], o0[1], o0[2], o0[3]);
        *reinterpret_cast<float4*>(o + 1*HH*WH) = make_float4(o1[0], o1[1], o1[2], o1[3]);
        *reinterpret_cast<float4*>(o + 2*HH*WH) = make_float4(o2[0], o2[1], o2[2], o2[3]);
        *reinterpret_cast<float4*>(o + 3*HH*WH) = make_float4(o3[0], o3[1], o3[2], o3[3]);
    }
}

extern "C" void kernel_launch(void* const* d_in, const int* in_sizes, int n_in,
                              void* d_out, int out_size)
{
    const float* x = (const float*)d_in[0];
    const float* w = (const float*)d_in[1];
    if (n_in >= 2 && in_sizes[0] == 4) {
        x = (const float*)d_in[1];
        w = (const float*)d_in[0];
    }
    float* out = (float*)d_out;

    quanv_kernel<<<NBLOCKS, NTHREADS>>>(x, w, out);
}

// round 7
// speedup vs baseline: 1.0922x; 1.0922x over previous
#include <cuda_runtime.h>

// QuanvLayer closed form:
//   z_i = cos(w_i) * cos(x_i)   (patch elements p00,p01,p10,p11)
//   out[q=0] = z1*z2*z3 ; out[q=1] = z0*z1 ; out[q=2] = z0*z1*z2 ; out[q=3] = z0*z1*z2*z3
//
// x: (128, 3, 128, 128) f32 ; weights: (1,4) f32 ; out: (128, 12, 64, 64) f32
//
// R7: persistent 1184x256 (R4 winner) + FRONT-BATCHED second chunk.
// stride 303104 = 296*1024, so chunk B = chunk A with bc+=296 (same h2,w8):
// B's loads are A's pointer + constant offset. Heavy threads (bc<88) issue all
// 8 LDG.128 before any compute -> second memory round trip hidden under A's
// compute/stores instead of serialized after it.

#define B_ 128
#define C_ 3
#define H_ 128
#define W_ 128
#define HH 64
#define WH 64

#define NBLOCKS 1184
#define NTHREADS 256
#define TOTAL_CHUNKS (B_ * C_ * HH * (WH / 4))   // 393216
#define STRIDE (NBLOCKS * NTHREADS)              // 303104
// second-chunk offset in floats: 296 * H_ * W_ = 296 * 16384
#define XOFF2 (296 * H_ * W_)
// second-chunk output offset: 4*296 planes * HH*WH
#define OOFF2 ((size_t)4 * 296 * HH * WH)

__device__ __forceinline__ void quanv_patch4(
    const float4& t0, const float4& t1, const float4& b0, const float4& b1,
    float cw0, float cw1, float cw2, float cw3, float* __restrict__ o)
{
    float top[8] = {t0.x, t0.y, t0.z, t0.w, t1.x, t1.y, t1.z, t1.w};
    float bot[8] = {b0.x, b0.y, b0.z, b0.w, b1.x, b1.y, b1.z, b1.w};
    float o0[4], o1[4], o2[4], o3[4];
    #pragma unroll
    for (int p = 0; p < 4; p++) {
        float z0 = cw0 * __cosf(top[2*p]);
        float z1 = cw1 * __cosf(top[2*p + 1]);
        float z2 = cw2 * __cosf(bot[2*p]);
        float z3 = cw3 * __cosf(bot[2*p + 1]);
        float q1 = z0 * z1;
        float q2 = q1 * z2;
        float q3 = q2 * z3;
        float q0 = z1 * z2 * z3;
        o0[p] = q0; o1[p] = q1; o2[p] = q2; o3[p] = q3;
    }
    *reinterpret_cast<float4*>(o)           = make_float4(o0[0], o0[1], o0[2], o0[3]);
    *reinterpret_cast<float4*>(o + 1*HH*WH) = make_float4(o1[0], o1[1], o1[2], o1[3]);
    *reinterpret_cast<float4*>(o + 2*HH*WH) = make_float4(o2[0], o2[1], o2[2], o2[3]);
    *reinterpret_cast<float4*>(o + 3*HH*WH) = make_float4(o3[0], o3[1], o3[2], o3[3]);
}

__global__ void __launch_bounds__(NTHREADS)
quanv_kernel(const float* __restrict__ x,
             const float* __restrict__ w,
             float* __restrict__ out)
{
    const float cw0 = __cosf(__ldg(w + 0));
    const float cw1 = __cosf(__ldg(w + 1));
    const float cw2 = __cosf(__ldg(w + 2));
    const float cw3 = __cosf(__ldg(w + 3));

    int tid = blockIdx.x * NTHREADS + threadIdx.x;

    // tid = (bc*HH + h2)*16 + w8 ; w8 covers 4 patches (8 input cols)
    int w8 = tid & 15;
    int h2 = (tid >> 4) & (HH - 1);
    int bc = tid >> 10;                          // b*C + c in [0, 296)
    bool heavy = (bc < 88);                      // second chunk exists (tid+303104 < 393216)

    const float* rowA = x + ((size_t)bc * H_ + 2 * h2) * W_ + 8 * w8;
    // chunk A loads
    const float4 At0 = *reinterpret_cast<const float4*>(rowA);
    const float4 At1 = *reinterpret_cast<const float4*>(rowA + 4);
    const float4 Ab0 = *reinterpret_cast<const float4*>(rowA + W_);
    const float4 Ab1 = *reinterpret_cast<const float4*>(rowA + W_ + 4);

    // chunk B loads (front-batched, hidden under A's compute)
    float4 Bt0, Bt1, Bb0, Bb1;
    const float* rowB = rowA + XOFF2;
    if (heavy) {
        Bt0 = *reinterpret_cast<const float4*>(rowB);
        Bt1 = *reinterpret_cast<const float4*>(rowB + 4);
        Bb0 = *reinterpret_cast<const float4*>(rowB + W_);
        Bb1 = *reinterpret_cast<const float4*>(rowB + W_ + 4);
    }

    // out base for chunk A: plane stride HH*WH = 4096
    float* oA = out + (((size_t)4 * bc) * HH + h2) * WH + 4 * w8;
    quanv_patch4(At0, At1, Ab0, Ab1, cw0, cw1, cw2, cw3, oA);

    if (heavy) {
        quanv_patch4(Bt0, Bt1, Bb0, Bb1, cw0, cw1, cw2, cw3, oA + OOFF2);
    }
}

extern "C" void kernel_launch(void* const* d_in, const int* in_sizes, int n_in,
                              void* d_out, int out_size)
{
    const float* x = (const float*)d_in[0];
    const float* w = (const float*)d_in[1];
    if (n_in >= 2 && in_sizes[0] == 4) {
        x = (const float*)d_in[1];
        w = (const float*)d_in[0];
    }
    float* out = (float*)d_out;

    quanv_kernel<<<NBLOCKS, NTHREADS>>>(x, w, out);
}